// round 3
// baseline (speedup 1.0000x reference)
#include <cuda_runtime.h>
#include <math.h>

#define NN 20000
#define NE 320000
#define D  128
#define H  12
#define HO 1536          // H * D
#define BN_EPS 1e-5f

// ---------------- scratch (device globals: no allocation allowed) ----------
__device__ float g_Y[(size_t)NN * HO];   // per-node per-head projections (123 MB)
__device__ float g_U[NN * H];            // per-node attention projections
__device__ float g_t[NN * D];            // post-relu, pre-BN
__device__ float g_h[NN * D];            // layer input features
__device__ float g_agg[NN * D];          // edge aggregation
__device__ int   g_deg[NN];
__device__ float g_sum[D];
__device__ float g_sumsq[D];

// ---------------- degree (identical for all layers) ------------------------
__global__ void deg_init_kernel() {
    int i = blockIdx.x * blockDim.x + threadIdx.x;
    if (i < NN) g_deg[i] = 1;            // self loop
}
__global__ void deg_count_kernel(const int* __restrict__ ei) {
    int e = blockIdx.x * blockDim.x + threadIdx.x;
    if (e < NE) atomicAdd(&g_deg[ei[NE + e]], 1);
}

// ---------------- zero agg + bn accumulators --------------------------------
__global__ void zero_kernel() {
    int i = blockIdx.x * blockDim.x + threadIdx.x;
    if (i < NN * D) g_agg[i] = 0.f;
    if (i < D) { g_sum[i] = 0.f; g_sumsq[i] = 0.f; }
}

// ---------------- SGEMM: Y[m,o] = sum_k A[m,k] * W[o,k] --------------------
// A: [M,128] row-major, W: [1536,128] row-major, Y: [M,1536]
__global__ __launch_bounds__(256) void gemm_y_kernel(
    const float* __restrict__ A, const float* __restrict__ W, int M)
{
    __shared__ float As[16][128];
    __shared__ float Bs[16][128];
    const int bm = blockIdx.y * 128;
    const int bo = blockIdx.x * 128;
    const int tid = threadIdx.x;
    const int tm = (tid >> 4) << 3;       // 0..120 step 8
    const int tn = (tid & 15) << 3;
    float acc[8][8];
#pragma unroll
    for (int i = 0; i < 8; i++)
#pragma unroll
        for (int j = 0; j < 8; j++) acc[i][j] = 0.f;

    for (int k0 = 0; k0 < 128; k0 += 16) {
#pragma unroll
        for (int it = 0; it < 2; it++) {
            int idx = tid + it * 256;       // 0..511 (float4 index)
            int r   = idx >> 2;             // 0..127
            int c   = (idx & 3) << 2;       // 0,4,8,12
            int row = bm + r;
            float4 va = make_float4(0.f, 0.f, 0.f, 0.f);
            if (row < M)
                va = *reinterpret_cast<const float4*>(A + (size_t)row * 128 + k0 + c);
            As[c + 0][r] = va.x; As[c + 1][r] = va.y;
            As[c + 2][r] = va.z; As[c + 3][r] = va.w;
            float4 vb = *reinterpret_cast<const float4*>(W + (size_t)(bo + r) * 128 + k0 + c);
            Bs[c + 0][r] = vb.x; Bs[c + 1][r] = vb.y;
            Bs[c + 2][r] = vb.z; Bs[c + 3][r] = vb.w;
        }
        __syncthreads();
#pragma unroll
        for (int k = 0; k < 16; k++) {
            float a[8], b[8];
            *reinterpret_cast<float4*>(a)     = *reinterpret_cast<const float4*>(&As[k][tm]);
            *reinterpret_cast<float4*>(a + 4) = *reinterpret_cast<const float4*>(&As[k][tm + 4]);
            *reinterpret_cast<float4*>(b)     = *reinterpret_cast<const float4*>(&Bs[k][tn]);
            *reinterpret_cast<float4*>(b + 4) = *reinterpret_cast<const float4*>(&Bs[k][tn + 4]);
#pragma unroll
            for (int i = 0; i < 8; i++)
#pragma unroll
                for (int j = 0; j < 8; j++) acc[i][j] += a[i] * b[j];
        }
        __syncthreads();
    }
#pragma unroll
    for (int i = 0; i < 8; i++) {
        int row = bm + tm + i;
        if (row < M) {
#pragma unroll
            for (int j = 0; j < 8; j += 4)
                *reinterpret_cast<float4*>(g_Y + (size_t)row * HO + bo + tn + j) =
                    *reinterpret_cast<float4*>(&acc[i][j]);
        }
    }
}

// ---------------- U[n,h] = sum_k X[n,k]*Wu[h,k]  (warp per node) -----------
__global__ void u_kernel(const float* __restrict__ X, const float* __restrict__ Wu, int M) {
    __shared__ float wu[H * D];
    for (int i = threadIdx.x; i < H * D; i += blockDim.x) wu[i] = Wu[i];
    __syncthreads();
    int warp = blockIdx.x * (blockDim.x >> 5) + (threadIdx.x >> 5);
    int lane = threadIdx.x & 31;
    if (warp >= M) return;
    const float* xr = X + (size_t)warp * D;
    float x0 = xr[lane], x1 = xr[lane + 32], x2 = xr[lane + 64], x3 = xr[lane + 96];
#pragma unroll
    for (int h = 0; h < H; h++) {
        float p = x0 * wu[h * D + lane] + x1 * wu[h * D + lane + 32]
                + x2 * wu[h * D + lane + 64] + x3 * wu[h * D + lane + 96];
#pragma unroll
        for (int o = 16; o; o >>= 1) p += __shfl_xor_sync(0xffffffffu, p, o);
        if (lane == 0) g_U[warp * H + h] = p;
    }
}

// ---------------- edge aggregation (warp per edge, incl. self loops) -------
__global__ void edge_kernel(const int* __restrict__ ei, const float* __restrict__ cvec) {
    int warp = blockIdx.x * (blockDim.x >> 5) + (threadIdx.x >> 5);
    int lane = threadIdx.x & 31;
    if (warp >= NE + NN) return;
    int s, d;
    if (warp < NE) { s = ei[warp]; d = ei[NE + warp]; }
    else           { s = warp - NE; d = s; }

    float logit = -1e30f;
    if (lane < H)
        logit = g_U[d * H + lane] - g_U[s * H + lane] + __ldg(&cvec[lane]);
    float m = logit;
#pragma unroll
    for (int o = 16; o; o >>= 1) m = fmaxf(m, __shfl_xor_sync(0xffffffffu, m, o));
    float e = (lane < H) ? __expf(logit - m) : 0.f;
    float ssum = e;
#pragma unroll
    for (int o = 16; o; o >>= 1) ssum += __shfl_xor_sync(0xffffffffu, ssum, o);
    float a = e / ssum;
    float att[H];
#pragma unroll
    for (int h = 0; h < H; h++) att[h] = __shfl_sync(0xffffffffu, a, h);

    const float4* y4 = reinterpret_cast<const float4*>(g_Y + (size_t)s * HO) + lane;
    float a0 = 0.f, a1 = 0.f, a2 = 0.f, a3 = 0.f;
#pragma unroll
    for (int h = 0; h < H; h++) {
        float4 v = y4[h * 32];
        a0 += att[h] * v.x; a1 += att[h] * v.y;
        a2 += att[h] * v.z; a3 += att[h] * v.w;
    }
    float* dst = g_agg + (size_t)d * D + lane * 4;
    atomicAdd(dst + 0, a0);
    atomicAdd(dst + 1, a1);
    atomicAdd(dst + 2, a2);
    atomicAdd(dst + 3, a3);
}

// ---------------- finalize: out = agg/deg + b, optional relu ----------------
__global__ void finalize_kernel(const float* __restrict__ bvec, float* __restrict__ out, int relu) {
    int i = blockIdx.x * blockDim.x + threadIdx.x;
    if (i >= NN * D) return;
    float v = g_agg[i] / (float)g_deg[i >> 7] + bvec[i & (D - 1)];
    if (relu) v = fmaxf(v, 0.f);
    out[i] = v;
}

// ---------------- batchnorm (training mode, biased var) ---------------------
__global__ void bn_stats_kernel(const float* __restrict__ t) {
    __shared__ float s1[256], s2[256];
    int c    = threadIdx.x & (D - 1);
    int part = threadIdx.x >> 7;     // 0/1
    float sum = 0.f, sq = 0.f;
    for (int r = blockIdx.x * 2 + part; r < NN; r += gridDim.x * 2) {
        float v = t[(size_t)r * D + c];
        sum += v; sq += v * v;
    }
    s1[threadIdx.x] = sum; s2[threadIdx.x] = sq;
    __syncthreads();
    if (part == 0) {
        atomicAdd(&g_sum[c],   s1[c] + s1[c + D]);
        atomicAdd(&g_sumsq[c], s2[c] + s2[c + D]);
    }
}

__global__ void bn_apply_kernel(const float* __restrict__ t,
                                const float* __restrict__ gam,
                                const float* __restrict__ bet,
                                float* __restrict__ out) {
    int i = blockIdx.x * blockDim.x + threadIdx.x;
    if (i >= NN * D) return;
    int c = i & (D - 1);
    const float invN = 1.f / (float)NN;
    float m = g_sum[c] * invN;
    float v = g_sumsq[c] * invN - m * m;
    out[i] = (t[i] - m) * rsqrtf(v + BN_EPS) * gam[c] + bet[c];
}

// ---------------- launch ----------------------------------------------------
static void run_layer(const float* in, const float* Wlin, const float* Wu,
                      const float* cvec, const float* bvec, const int* ei,
                      float* outbuf, int relu)
{
    dim3 ggrid(HO / 128, (NN + 127) / 128);
    gemm_y_kernel<<<ggrid, 256>>>(in, Wlin, NN);
    u_kernel<<<(NN * 32 + 255) / 256, 256>>>(in, Wu, NN);
    zero_kernel<<<(NN * D + 255) / 256, 256>>>();
    int nwarp = NE + NN;
    edge_kernel<<<(nwarp * 32 + 255) / 256, 256>>>(ei, cvec);
    finalize_kernel<<<(NN * D + 255) / 256, 256>>>(bvec, outbuf, relu);
}

extern "C" void kernel_launch(void* const* d_in, const int* in_sizes, int n_in,
                              void* d_out, int out_size)
{
    const float* x  = (const float*)d_in[0];
    const int*   ei = (const int*)d_in[1];

    const float *Wlin[3], *Wu[3], *cv[3], *bv[3], *bng[2], *bnb[2];
    if (in_sizes[6] == H * D * D) {
        // dict-insertion order: l0(4), l1(4), l2(4), bn0_g, bn0_b, bn1_g, bn1_b
        for (int l = 0; l < 3; l++) {
            Wlin[l] = (const float*)d_in[2 + 4 * l];
            Wu[l]   = (const float*)d_in[3 + 4 * l];
            cv[l]   = (const float*)d_in[4 + 4 * l];
            bv[l]   = (const float*)d_in[5 + 4 * l];
        }
        bng[0] = (const float*)d_in[14]; bnb[0] = (const float*)d_in[15];
        bng[1] = (const float*)d_in[16]; bnb[1] = (const float*)d_in[17];
    } else {
        // reference-signature order: l0(4), bn0(2), l1(4), bn1(2), l2(4)
        Wlin[0] = (const float*)d_in[2];  Wu[0] = (const float*)d_in[3];
        cv[0]   = (const float*)d_in[4];  bv[0] = (const float*)d_in[5];
        bng[0]  = (const float*)d_in[6];  bnb[0] = (const float*)d_in[7];
        Wlin[1] = (const float*)d_in[8];  Wu[1] = (const float*)d_in[9];
        cv[1]   = (const float*)d_in[10]; bv[1] = (const float*)d_in[11];
        bng[1]  = (const float*)d_in[12]; bnb[1] = (const float*)d_in[13];
        Wlin[2] = (const float*)d_in[14]; Wu[2] = (const float*)d_in[15];
        cv[2]   = (const float*)d_in[16]; bv[2] = (const float*)d_in[17];
    }

    float* out = (float*)d_out;

    // degree (same for all layers)
    deg_init_kernel<<<(NN + 255) / 256, 256>>>();
    deg_count_kernel<<<(NE + 255) / 256, 256>>>(ei);

    // device-global pointers usable from host launch args
    float* t = nullptr; float* hbuf = nullptr;
    cudaGetSymbolAddress((void**)&t, g_t);
    cudaGetSymbolAddress((void**)&hbuf, g_h);

    // layer 0
    run_layer(x, Wlin[0], Wu[0], cv[0], bv[0], ei, t, 1);
    bn_stats_kernel<<<128, 256>>>(t);
    bn_apply_kernel<<<(NN * D + 255) / 256, 256>>>(t, bng[0], bnb[0], hbuf);

    // layer 1
    run_layer(hbuf, Wlin[1], Wu[1], cv[1], bv[1], ei, t, 1);
    bn_stats_kernel<<<128, 256>>>(t);
    bn_apply_kernel<<<(NN * D + 255) / 256, 256>>>(t, bng[1], bnb[1], hbuf);

    // layer 2 (no relu, no BN) -> d_out
    run_layer(hbuf, Wlin[2], Wu[2], cv[2], bv[2], ei, out, 0);
}

// round 4
// speedup vs baseline: 1.2246x; 1.2246x over previous
#include <cuda_runtime.h>
#include <math.h>

#define NN 20000
#define NE 320000
#define D  128
#define H  12
#define HO 1536          // H * D
#define BN_EPS 1e-5f

typedef unsigned long long u64;

// ---------------- packed f32x2 helpers (FFMA2 is PTX-only) -----------------
__device__ __forceinline__ u64 pack2(float lo, float hi) {
    u64 r; asm("mov.b64 %0, {%1,%2};" : "=l"(r) : "f"(lo), "f"(hi)); return r;
}
__device__ __forceinline__ u64 ffma2(u64 a, u64 b, u64 c) {
    u64 d; asm("fma.rn.f32x2 %0, %1, %2, %3;" : "=l"(d) : "l"(a), "l"(b), "l"(c)); return d;
}
__device__ __forceinline__ void unpack2(u64 v, float& lo, float& hi) {
    asm("mov.b64 {%0,%1}, %2;" : "=f"(lo), "=f"(hi) : "l"(v));
}
__device__ __forceinline__ void red_add_v4(float* p, float a, float b, float c, float d) {
    asm volatile("red.global.add.v4.f32 [%0], {%1,%2,%3,%4};"
                 :: "l"(p), "f"(a), "f"(b), "f"(c), "f"(d) : "memory");
}

union F4U { float4 f; u64 u[2]; };

// ---------------- scratch (device globals: no allocation allowed) ----------
__device__ float g_Y[(size_t)NN * HO];   // per-node per-head projections (123 MB)
__device__ float g_U[NN * H];            // per-node attention projections
__device__ float g_t[NN * D];            // post-relu, pre-BN
__device__ float g_h[NN * D];            // layer input features
__device__ float g_agg[NN * D];          // edge aggregation
__device__ int   g_deg[NN];              // in-degree (incl self loop)
__device__ float g_sum[D];
__device__ float g_sumsq[D];
// CSR by src (built once per launch; edge list identical across layers)
__device__ int   g_rowptr[NN + 1];
__device__ int   g_cnt[NN];
__device__ int   g_adj[NE];

// ---------------- degree (by dst, for the mean) -----------------------------
__global__ void deg_init_kernel() {
    int i = blockIdx.x * blockDim.x + threadIdx.x;
    if (i < NN) g_deg[i] = 1;            // self loop
}
__global__ void deg_count_kernel(const int* __restrict__ ei) {
    int e = blockIdx.x * blockDim.x + threadIdx.x;
    if (e < NE) atomicAdd(&g_deg[ei[NE + e]], 1);
}

// ---------------- CSR build (by src) ----------------------------------------
__global__ void csr_zero_kernel() {
    int i = blockIdx.x * blockDim.x + threadIdx.x;
    if (i < NN) g_cnt[i] = 0;
}
__global__ void csr_count_kernel(const int* __restrict__ ei) {
    int e = blockIdx.x * blockDim.x + threadIdx.x;
    if (e < NE) atomicAdd(&g_cnt[ei[e]], 1);       // count by SRC
}
__global__ void csr_scan_kernel() {
    __shared__ int sh[1024];
    __shared__ int carry;
    if (threadIdx.x == 0) { carry = 0; g_rowptr[0] = 0; }
    __syncthreads();
    for (int base = 0; base < NN; base += 1024) {
        int i = base + threadIdx.x;
        int v = (i < NN) ? g_cnt[i] : 0;
        sh[threadIdx.x] = v;
        __syncthreads();
        for (int o = 1; o < 1024; o <<= 1) {
            int t = (threadIdx.x >= o) ? sh[threadIdx.x - o] : 0;
            __syncthreads();
            sh[threadIdx.x] += t;
            __syncthreads();
        }
        int base_off = carry;                    // read before update
        __syncthreads();
        if (i < NN) g_rowptr[i + 1] = base_off + sh[threadIdx.x];
        __syncthreads();
        if (threadIdx.x == 0) carry = base_off + sh[1023];
        __syncthreads();
    }
}
__global__ void csr_fill_kernel(const int* __restrict__ ei) {
    int e = blockIdx.x * blockDim.x + threadIdx.x;
    if (e >= NE) return;
    int s = ei[e];
    int pos = atomicAdd(&g_cnt[s], 1);           // g_cnt re-zeroed before fill
    g_adj[g_rowptr[s] + pos] = ei[NE + e];
}

// ---------------- zero agg + bn accumulators --------------------------------
__global__ void zero_kernel() {
    int i = blockIdx.x * blockDim.x + threadIdx.x;
    if (i < NN * D) g_agg[i] = 0.f;
    if (i < D) { g_sum[i] = 0.f; g_sumsq[i] = 0.f; }
}

// ---------------- SGEMM: Y[m,o] = sum_k A[m,k] * W[o,k]  (FFMA2 inner) ------
// A: [M,128] row-major, W: [1536,128] row-major, Y: [M,1536]
__global__ __launch_bounds__(256) void gemm_y_kernel(
    const float* __restrict__ A, const float* __restrict__ W, int M)
{
    __shared__ float As[16][128];
    __shared__ float Bs[16][128];
    const int bm = blockIdx.y * 128;
    const int bo = blockIdx.x * 128;
    const int tid = threadIdx.x;
    const int tm = (tid >> 4) << 3;       // 0..120 step 8
    const int tn = (tid & 15) << 3;

    u64 acc2[8][4];
#pragma unroll
    for (int i = 0; i < 8; i++)
#pragma unroll
        for (int j = 0; j < 4; j++) acc2[i][j] = 0ull;

    // per-tile load coords
    const int r  = tid >> 2;              // 0..127 (shared by both it steps via +64)
    const int c  = (tid & 3) << 2;        // 0,4,8,12

    float4 pva[2], pvb[2];
    // prefetch tile k0 = 0
#pragma unroll
    for (int it = 0; it < 2; it++) {
        int rr = r + it * 64;
        int row = bm + rr;
        pva[it] = make_float4(0.f, 0.f, 0.f, 0.f);
        if (row < M)
            pva[it] = *reinterpret_cast<const float4*>(A + (size_t)row * 128 + c);
        pvb[it] = *reinterpret_cast<const float4*>(W + (size_t)(bo + rr) * 128 + c);
    }

    for (int k0 = 0; k0 < 128; k0 += 16) {
#pragma unroll
        for (int it = 0; it < 2; it++) {
            int rr = r + it * 64;
            As[c + 0][rr] = pva[it].x; As[c + 1][rr] = pva[it].y;
            As[c + 2][rr] = pva[it].z; As[c + 3][rr] = pva[it].w;
            Bs[c + 0][rr] = pvb[it].x; Bs[c + 1][rr] = pvb[it].y;
            Bs[c + 2][rr] = pvb[it].z; Bs[c + 3][rr] = pvb[it].w;
        }
        __syncthreads();

        // prefetch next tile while computing
        if (k0 + 16 < 128) {
#pragma unroll
            for (int it = 0; it < 2; it++) {
                int rr = r + it * 64;
                int row = bm + rr;
                pva[it] = make_float4(0.f, 0.f, 0.f, 0.f);
                if (row < M)
                    pva[it] = *reinterpret_cast<const float4*>(A + (size_t)row * 128 + k0 + 16 + c);
                pvb[it] = *reinterpret_cast<const float4*>(W + (size_t)(bo + rr) * 128 + k0 + 16 + c);
            }
        }

#pragma unroll
        for (int k = 0; k < 16; k++) {
            float a[8]; u64 b2[4];
            *reinterpret_cast<float4*>(a)     = *reinterpret_cast<const float4*>(&As[k][tm]);
            *reinterpret_cast<float4*>(a + 4) = *reinterpret_cast<const float4*>(&As[k][tm + 4]);
            const u64* bp = reinterpret_cast<const u64*>(&Bs[k][tn]);
            b2[0] = bp[0]; b2[1] = bp[1]; b2[2] = bp[2]; b2[3] = bp[3];
#pragma unroll
            for (int i = 0; i < 8; i++) {
                u64 av = pack2(a[i], a[i]);
#pragma unroll
                for (int j = 0; j < 4; j++)
                    acc2[i][j] = ffma2(av, b2[j], acc2[i][j]);
            }
        }
        __syncthreads();
    }

#pragma unroll
    for (int i = 0; i < 8; i++) {
        int row = bm + tm + i;
        if (row < M) {
            float o[8];
#pragma unroll
            for (int j = 0; j < 4; j++) unpack2(acc2[i][j], o[2 * j], o[2 * j + 1]);
            float* dst = g_Y + (size_t)row * HO + bo + tn;
            *reinterpret_cast<float4*>(dst)     = *reinterpret_cast<float4*>(o);
            *reinterpret_cast<float4*>(dst + 4) = *reinterpret_cast<float4*>(o + 4);
        }
    }
}

// ---------------- U[n,h] = sum_k X[n,k]*Wu[h,k]  (warp per node) -----------
__global__ void u_kernel(const float* __restrict__ X, const float* __restrict__ Wu, int M) {
    __shared__ float wu[H * D];
    for (int i = threadIdx.x; i < H * D; i += blockDim.x) wu[i] = Wu[i];
    __syncthreads();
    int warp = blockIdx.x * (blockDim.x >> 5) + (threadIdx.x >> 5);
    int lane = threadIdx.x & 31;
    if (warp >= M) return;
    const float* xr = X + (size_t)warp * D;
    float x0 = xr[lane], x1 = xr[lane + 32], x2 = xr[lane + 64], x3 = xr[lane + 96];
#pragma unroll
    for (int h = 0; h < H; h++) {
        float p = x0 * wu[h * D + lane] + x1 * wu[h * D + lane + 32]
                + x2 * wu[h * D + lane + 64] + x3 * wu[h * D + lane + 96];
#pragma unroll
        for (int o = 16; o; o >>= 1) p += __shfl_xor_sync(0xffffffffu, p, o);
        if (lane == 0) g_U[warp * H + h] = p;
    }
}

// ---------------- scatter: warp per SRC node, Y row in registers ------------
__global__ __launch_bounds__(256) void scatter_kernel(const float* __restrict__ cvec) {
    int warp = blockIdx.x * 8 + (threadIdx.x >> 5);
    int lane = threadIdx.x & 31;
    if (warp >= NN) return;
    const int s = warp;

    F4U yv[H];
    const float4* y4 = reinterpret_cast<const float4*>(g_Y + (size_t)s * HO) + lane;
#pragma unroll
    for (int h = 0; h < H; h++) yv[h].f = y4[h * 32];

    float us = 0.f, cl = 0.f;
    if (lane < H) { us = g_U[s * H + lane]; cl = __ldg(&cvec[lane]); }

    int row = g_rowptr[s], end = g_rowptr[s + 1];
    // i == row-1 encodes the self loop (dst = s, U[d]-U[s] = 0)
    for (int i = row - 1; i < end; i++) {
        int d = s;
        float ud = us;
        if (i >= row) {
            d = g_adj[i];
            ud = (lane < H) ? __ldg(&g_U[d * H + lane]) : 0.f;
        }
        float logit = (lane < H) ? (ud - us + cl) : -1e30f;
        float m = logit;
#pragma unroll
        for (int o = 16; o; o >>= 1) m = fmaxf(m, __shfl_xor_sync(0xffffffffu, m, o));
        float e = (lane < H) ? __expf(logit - m) : 0.f;
        float ss = e;
#pragma unroll
        for (int o = 16; o; o >>= 1) ss += __shfl_xor_sync(0xffffffffu, ss, o);
        float a = e / ss;

        u64 m0 = 0ull, m1 = 0ull;
#pragma unroll
        for (int h = 0; h < H; h++) {
            float ah = __shfl_sync(0xffffffffu, a, h);
            u64 a2 = pack2(ah, ah);
            m0 = ffma2(a2, yv[h].u[0], m0);
            m1 = ffma2(a2, yv[h].u[1], m1);
        }
        float r0, r1, r2, r3;
        unpack2(m0, r0, r1);
        unpack2(m1, r2, r3);
        red_add_v4(g_agg + (size_t)d * D + lane * 4, r0, r1, r2, r3);
    }
}

// ---------------- finalize: out = agg/deg + b, optional relu ----------------
__global__ void finalize_kernel(const float* __restrict__ bvec, float* __restrict__ out, int relu) {
    int i = blockIdx.x * blockDim.x + threadIdx.x;
    if (i >= NN * D) return;
    float v = g_agg[i] / (float)g_deg[i >> 7] + bvec[i & (D - 1)];
    if (relu) v = fmaxf(v, 0.f);
    out[i] = v;
}

// ---------------- batchnorm (training mode, biased var) ---------------------
__global__ void bn_stats_kernel(const float* __restrict__ t) {
    __shared__ float s1[256], s2[256];
    int c    = threadIdx.x & (D - 1);
    int part = threadIdx.x >> 7;     // 0/1
    float sum = 0.f, sq = 0.f;
    for (int r = blockIdx.x * 2 + part; r < NN; r += gridDim.x * 2) {
        float v = t[(size_t)r * D + c];
        sum += v; sq += v * v;
    }
    s1[threadIdx.x] = sum; s2[threadIdx.x] = sq;
    __syncthreads();
    if (part == 0) {
        atomicAdd(&g_sum[c],   s1[c] + s1[c + D]);
        atomicAdd(&g_sumsq[c], s2[c] + s2[c + D]);
    }
}

__global__ void bn_apply_kernel(const float* __restrict__ t,
                                const float* __restrict__ gam,
                                const float* __restrict__ bet,
                                float* __restrict__ out) {
    int i = blockIdx.x * blockDim.x + threadIdx.x;
    if (i >= NN * D) return;
    int c = i & (D - 1);
    const float invN = 1.f / (float)NN;
    float m = g_sum[c] * invN;
    float v = g_sumsq[c] * invN - m * m;
    out[i] = (t[i] - m) * rsqrtf(v + BN_EPS) * gam[c] + bet[c];
}

// ---------------- launch ----------------------------------------------------
static void run_layer(const float* in, const float* Wlin, const float* Wu,
                      const float* cvec, const float* bvec,
                      float* outbuf, int relu)
{
    dim3 ggrid(HO / 128, (NN + 127) / 128);
    gemm_y_kernel<<<ggrid, 256>>>(in, Wlin, NN);
    u_kernel<<<(NN * 32 + 255) / 256, 256>>>(in, Wu, NN);
    zero_kernel<<<(NN * D + 255) / 256, 256>>>();
    scatter_kernel<<<(NN + 7) / 8, 256>>>(cvec);
    finalize_kernel<<<(NN * D + 255) / 256, 256>>>(bvec, outbuf, relu);
}

extern "C" void kernel_launch(void* const* d_in, const int* in_sizes, int n_in,
                              void* d_out, int out_size)
{
    const float* x  = (const float*)d_in[0];
    const int*   ei = (const int*)d_in[1];

    const float *Wlin[3], *Wu[3], *cv[3], *bv[3], *bng[2], *bnb[2];
    if (in_sizes[6] == H * D * D) {
        // dict-insertion order: l0(4), l1(4), l2(4), bn0_g, bn0_b, bn1_g, bn1_b
        for (int l = 0; l < 3; l++) {
            Wlin[l] = (const float*)d_in[2 + 4 * l];
            Wu[l]   = (const float*)d_in[3 + 4 * l];
            cv[l]   = (const float*)d_in[4 + 4 * l];
            bv[l]   = (const float*)d_in[5 + 4 * l];
        }
        bng[0] = (const float*)d_in[14]; bnb[0] = (const float*)d_in[15];
        bng[1] = (const float*)d_in[16]; bnb[1] = (const float*)d_in[17];
    } else {
        // reference-signature order: l0(4), bn0(2), l1(4), bn1(2), l2(4)
        Wlin[0] = (const float*)d_in[2];  Wu[0] = (const float*)d_in[3];
        cv[0]   = (const float*)d_in[4];  bv[0] = (const float*)d_in[5];
        bng[0]  = (const float*)d_in[6];  bnb[0] = (const float*)d_in[7];
        Wlin[1] = (const float*)d_in[8];  Wu[1] = (const float*)d_in[9];
        cv[1]   = (const float*)d_in[10]; bv[1] = (const float*)d_in[11];
        bng[1]  = (const float*)d_in[12]; bnb[1] = (const float*)d_in[13];
        Wlin[2] = (const float*)d_in[14]; Wu[2] = (const float*)d_in[15];
        cv[2]   = (const float*)d_in[16]; bv[2] = (const float*)d_in[17];
    }

    float* out = (float*)d_out;

    // degree by dst (same for all layers)
    deg_init_kernel<<<(NN + 255) / 256, 256>>>();
    deg_count_kernel<<<(NE + 255) / 256, 256>>>(ei);

    // CSR by src (same for all layers)
    csr_zero_kernel<<<(NN + 255) / 256, 256>>>();
    csr_count_kernel<<<(NE + 255) / 256, 256>>>(ei);
    csr_scan_kernel<<<1, 1024>>>();
    csr_zero_kernel<<<(NN + 255) / 256, 256>>>();
    csr_fill_kernel<<<(NE + 255) / 256, 256>>>(ei);

    // device-global pointers usable as kernel args
    float* t = nullptr; float* hbuf = nullptr;
    cudaGetSymbolAddress((void**)&t, g_t);
    cudaGetSymbolAddress((void**)&hbuf, g_h);

    // layer 0
    run_layer(x, Wlin[0], Wu[0], cv[0], bv[0], t, 1);
    bn_stats_kernel<<<128, 256>>>(t);
    bn_apply_kernel<<<(NN * D + 255) / 256, 256>>>(t, bng[0], bnb[0], hbuf);

    // layer 1
    run_layer(hbuf, Wlin[1], Wu[1], cv[1], bv[1], t, 1);
    bn_stats_kernel<<<128, 256>>>(t);
    bn_apply_kernel<<<(NN * D + 255) / 256, 256>>>(t, bng[1], bnb[1], hbuf);

    // layer 2 (no relu, no BN) -> d_out
    run_layer(hbuf, Wlin[2], Wu[2], cv[2], bv[2], out, 0);
}

// round 6
// speedup vs baseline: 1.4891x; 1.2160x over previous
#include <cuda_runtime.h>
#include <cuda_bf16.h>
#include <math.h>
#include <cstdint>

#define NN 20000
#define NE 320000
#define D  128
#define H  12
#define HO 1536          // H * D
#define BN_EPS 1e-5f
#define MPAD 20096       // 157 * 128
#define KT 384           // 3 * 128 (bf16 double-split emulated fp32 GEMM)
#define LDS_PAD 72       // smem row stride in bf16 elements (144 B)

typedef unsigned long long u64;
typedef uint32_t u32;

// ---------------- packed f32x2 helpers --------------------------------------
__device__ __forceinline__ u64 pack2(float lo, float hi) {
    u64 r; asm("mov.b64 %0, {%1,%2};" : "=l"(r) : "f"(lo), "f"(hi)); return r;
}
__device__ __forceinline__ u64 ffma2(u64 a, u64 b, u64 c) {
    u64 d; asm("fma.rn.f32x2 %0, %1, %2, %3;" : "=l"(d) : "l"(a), "l"(b), "l"(c)); return d;
}
__device__ __forceinline__ void unpack2(u64 v, float& lo, float& hi) {
    asm("mov.b64 {%0,%1}, %2;" : "=f"(lo), "=f"(hi) : "l"(v));
}
__device__ __forceinline__ void red_add_v4(float* p, float a, float b, float c, float d) {
    asm volatile("red.global.add.v4.f32 [%0], {%1,%2,%3,%4};"
                 :: "l"(p), "f"(a), "f"(b), "f"(c), "f"(d) : "memory");
}
union F4U { float4 f; u64 u[2]; };

// ---------------- scratch (device globals) ----------------------------------
__device__ __nv_bfloat16 g_Abig[(size_t)MPAD * KT];   // [row, 384] = [hi|hi|lo]
__device__ __nv_bfloat16 g_Bbig[(size_t)HO * KT];     // [out, 384] = [hi|lo|hi]
__device__ float g_Y[(size_t)NN * HO];
__device__ float g_U[NN * H];
__device__ float g_t[NN * D];
__device__ float g_h[NN * D];
__device__ float g_agg[NN * D];
__device__ int   g_deg[NN];
__device__ float g_sum[D];
__device__ float g_sumsq[D];
__device__ int   g_rowptr[NN + 1];
__device__ int   g_cnt[NN];
__device__ int   g_adj[NE];

// ---------------- degree / CSR (built once) ---------------------------------
__global__ void deg_init_kernel() {
    int i = blockIdx.x * blockDim.x + threadIdx.x;
    if (i < NN) g_deg[i] = 1;
}
__global__ void deg_count_kernel(const int* __restrict__ ei) {
    int e = blockIdx.x * blockDim.x + threadIdx.x;
    if (e < NE) atomicAdd(&g_deg[ei[NE + e]], 1);
}
__global__ void csr_zero_kernel() {
    int i = blockIdx.x * blockDim.x + threadIdx.x;
    if (i < NN) g_cnt[i] = 0;
}
__global__ void csr_count_kernel(const int* __restrict__ ei) {
    int e = blockIdx.x * blockDim.x + threadIdx.x;
    if (e < NE) atomicAdd(&g_cnt[ei[e]], 1);
}
__global__ void csr_scan_kernel() {
    __shared__ int sh[1024];
    __shared__ int carry;
    if (threadIdx.x == 0) { carry = 0; g_rowptr[0] = 0; }
    __syncthreads();
    for (int base = 0; base < NN; base += 1024) {
        int i = base + threadIdx.x;
        int v = (i < NN) ? g_cnt[i] : 0;
        sh[threadIdx.x] = v;
        __syncthreads();
        for (int o = 1; o < 1024; o <<= 1) {
            int t = (threadIdx.x >= o) ? sh[threadIdx.x - o] : 0;
            __syncthreads();
            sh[threadIdx.x] += t;
            __syncthreads();
        }
        int base_off = carry;
        __syncthreads();
        if (i < NN) g_rowptr[i + 1] = base_off + sh[threadIdx.x];
        __syncthreads();
        if (threadIdx.x == 0) carry = base_off + sh[1023];
        __syncthreads();
    }
}
__global__ void csr_fill_kernel(const int* __restrict__ ei) {
    int e = blockIdx.x * blockDim.x + threadIdx.x;
    if (e >= NE) return;
    int s = ei[e];
    int pos = atomicAdd(&g_cnt[s], 1);
    g_adj[g_rowptr[s] + pos] = ei[NE + e];
}

// ---------------- zero agg + bn accumulators --------------------------------
__global__ void zero_kernel() {
    int i = blockIdx.x * blockDim.x + threadIdx.x;
    if (i < NN * D) g_agg[i] = 0.f;
    if (i < D) { g_sum[i] = 0.f; g_sumsq[i] = 0.f; }
}

// ---------------- input converts (bf16 double split) ------------------------
__global__ void convertx_kernel(const float* __restrict__ X) {
    int i = blockIdx.x * blockDim.x + threadIdx.x;
    if (i >= MPAD * D) return;
    int n = i >> 7, c = i & 127;
    float v = (n < NN) ? X[i] : 0.f;
    __nv_bfloat16 hi = __float2bfloat16(v);
    __nv_bfloat16 lo = __float2bfloat16(v - __bfloat162float(hi));
    size_t base = (size_t)n * KT + c;
    g_Abig[base]       = hi;
    g_Abig[base + 128] = hi;
    g_Abig[base + 256] = lo;
}
// fused BN apply + split convert (also emits fp32 g_h for u_kernel)
__global__ void bnconvert_kernel(const float* __restrict__ t,
                                 const float* __restrict__ gam,
                                 const float* __restrict__ bet) {
    int i = blockIdx.x * blockDim.x + threadIdx.x;
    if (i >= MPAD * D) return;
    int n = i >> 7, c = i & 127;
    float v = 0.f;
    if (n < NN) {
        const float invN = 1.f / (float)NN;
        float m  = g_sum[c] * invN;
        float vr = g_sumsq[c] * invN - m * m;
        v = (t[i] - m) * rsqrtf(vr + BN_EPS) * gam[c] + bet[c];
        g_h[i] = v;
    }
    __nv_bfloat16 hi = __float2bfloat16(v);
    __nv_bfloat16 lo = __float2bfloat16(v - __bfloat162float(hi));
    size_t base = (size_t)n * KT + c;
    g_Abig[base]       = hi;
    g_Abig[base + 128] = hi;
    g_Abig[base + 256] = lo;
}
__global__ void convertw_kernel(const float* __restrict__ W) {
    int i = blockIdx.x * blockDim.x + threadIdx.x;
    if (i >= HO * D) return;
    int o = i >> 7, c = i & 127;
    float v = W[i];
    __nv_bfloat16 hi = __float2bfloat16(v);
    __nv_bfloat16 lo = __float2bfloat16(v - __bfloat162float(hi));
    size_t base = (size_t)o * KT + c;
    g_Bbig[base]       = hi;
    g_Bbig[base + 128] = lo;
    g_Bbig[base + 256] = hi;
}

// ---------------- mma.sync GEMM: Y[m,o] = sum_k Abig[m,k]*Bbig[o,k] ---------
// grid (12, 157), 256 threads (8 warps, 2x4). CTA tile M=128, N=128, K=384.
// Warp tile 64x32: 4 m-frags (m16) x 4 n-frags (n8), k16 steps.
__global__ __launch_bounds__(256) void mma_y_kernel() {
    __shared__ __nv_bfloat16 As[128 * LDS_PAD];
    __shared__ __nv_bfloat16 Bs[128 * LDS_PAD];

    const int tid  = threadIdx.x;
    const int wid  = tid >> 5, lane = tid & 31;
    const int wm   = (wid >> 2) * 64;        // warp M offset: 0 / 64
    const int wn   = (wid & 3) * 32;         // warp N offset: 0/32/64/96
    const int bm   = blockIdx.y * 128;
    const int bo   = blockIdx.x * 128;
    const int g    = lane >> 2;              // 0..7
    const int tq   = lane & 3;               // 0..3

    float acc[4][4][4];
#pragma unroll
    for (int i = 0; i < 4; i++)
#pragma unroll
        for (int j = 0; j < 4; j++)
#pragma unroll
            for (int q = 0; q < 4; q++) acc[i][j][q] = 0.f;

    const int lr = tid >> 1;                 // load row 0..127
    const int lc = (tid & 1) * 32;           // 0 / 32 (elements)

    for (int ch = 0; ch < 6; ch++) {
        if (ch) __syncthreads();
        const __nv_bfloat16* ga = g_Abig + (size_t)(bm + lr) * KT + ch * 64 + lc;
        const __nv_bfloat16* gb = g_Bbig + (size_t)(bo + lr) * KT + ch * 64 + lc;
        __nv_bfloat16* sa = As + lr * LDS_PAD + lc;
        __nv_bfloat16* sb = Bs + lr * LDS_PAD + lc;
#pragma unroll
        for (int j = 0; j < 4; j++) {
            *(uint4*)(sa + j * 8) = *(const uint4*)(ga + j * 8);
            *(uint4*)(sb + j * 8) = *(const uint4*)(gb + j * 8);
        }
        __syncthreads();

#pragma unroll
        for (int k = 0; k < 4; k++) {
            const int kc = k * 16 + tq * 2;
            u32 a[4][4], b[4][2];
#pragma unroll
            for (int i = 0; i < 4; i++) {
                const __nv_bfloat16* ap = As + (wm + i * 16 + g) * LDS_PAD + kc;
                a[i][0] = *(const u32*)(ap);
                a[i][1] = *(const u32*)(ap + 8 * LDS_PAD);
                a[i][2] = *(const u32*)(ap + 8);
                a[i][3] = *(const u32*)(ap + 8 * LDS_PAD + 8);
            }
#pragma unroll
            for (int j = 0; j < 4; j++) {
                const __nv_bfloat16* bp = Bs + (wn + j * 8 + g) * LDS_PAD + kc;
                b[j][0] = *(const u32*)(bp);
                b[j][1] = *(const u32*)(bp + 8);
            }
#pragma unroll
            for (int i = 0; i < 4; i++)
#pragma unroll
                for (int j = 0; j < 4; j++) {
                    asm volatile(
                        "mma.sync.aligned.m16n8k16.row.col.f32.bf16.bf16.f32 "
                        "{%0,%1,%2,%3}, {%4,%5,%6,%7}, {%8,%9}, {%0,%1,%2,%3};"
                        : "+f"(acc[i][j][0]), "+f"(acc[i][j][1]),
                          "+f"(acc[i][j][2]), "+f"(acc[i][j][3])
                        : "r"(a[i][0]), "r"(a[i][1]), "r"(a[i][2]), "r"(a[i][3]),
                          "r"(b[j][0]), "r"(b[j][1]));
                }
        }
    }

    // epilogue: C frag thread t holds (row g, col tq*2 +0/1) and (row g+8, ...)
#pragma unroll
    for (int i = 0; i < 4; i++) {
        int r0 = bm + wm + i * 16 + g;
        int r1 = r0 + 8;
#pragma unroll
        for (int j = 0; j < 4; j++) {
            int col = bo + wn + j * 8 + tq * 2;
            if (r0 < NN)
                *(float2*)(g_Y + (size_t)r0 * HO + col) = make_float2(acc[i][j][0], acc[i][j][1]);
            if (r1 < NN)
                *(float2*)(g_Y + (size_t)r1 * HO + col) = make_float2(acc[i][j][2], acc[i][j][3]);
        }
    }
}

// ---------------- U[n,h] = sum_k X[n,k]*Wu[h,k]  (warp per node) ------------
__global__ void u_kernel(const float* __restrict__ X, const float* __restrict__ Wu, int M) {
    __shared__ float wu[H * D];
    for (int i = threadIdx.x; i < H * D; i += blockDim.x) wu[i] = Wu[i];
    __syncthreads();
    int warp = blockIdx.x * (blockDim.x >> 5) + (threadIdx.x >> 5);
    int lane = threadIdx.x & 31;
    if (warp >= M) return;
    const float* xr = X + (size_t)warp * D;
    float x0 = xr[lane], x1 = xr[lane + 32], x2 = xr[lane + 64], x3 = xr[lane + 96];
#pragma unroll
    for (int h = 0; h < H; h++) {
        float p = x0 * wu[h * D + lane] + x1 * wu[h * D + lane + 32]
                + x2 * wu[h * D + lane + 64] + x3 * wu[h * D + lane + 96];
#pragma unroll
        for (int o = 16; o; o >>= 1) p += __shfl_xor_sync(0xffffffffu, p, o);
        if (lane == 0) g_U[warp * H + h] = p;
    }
}

// ---------------- scatter: warp per SRC node, Y row in registers ------------
__global__ __launch_bounds__(256) void scatter_kernel(const float* __restrict__ cvec) {
    int warp = blockIdx.x * 8 + (threadIdx.x >> 5);
    int lane = threadIdx.x & 31;
    if (warp >= NN) return;
    const int s = warp;

    F4U yv[H];
    const float4* y4 = reinterpret_cast<const float4*>(g_Y + (size_t)s * HO) + lane;
#pragma unroll
    for (int h = 0; h < H; h++) yv[h].f = y4[h * 32];

    float us = 0.f, cl = 0.f;
    if (lane < H) { us = g_U[s * H + lane]; cl = __ldg(&cvec[lane]); }

    int row = g_rowptr[s], end = g_rowptr[s + 1];
    for (int i = row - 1; i < end; i++) {     // i == row-1 encodes the self loop
        int d = s;
        float ud = us;
        if (i >= row) {
            d = g_adj[i];
            ud = (lane < H) ? __ldg(&g_U[d * H + lane]) : 0.f;
        }
        float logit = (lane < H) ? (ud - us + cl) : -1e30f;
        float m = logit;
#pragma unroll
        for (int o = 16; o; o >>= 1) m = fmaxf(m, __shfl_xor_sync(0xffffffffu, m, o));
        float e = (lane < H) ? __expf(logit - m) : 0.f;
        float ss = e;
#pragma unroll
        for (int o = 16; o; o >>= 1) ss += __shfl_xor_sync(0xffffffffu, ss, o);
        float a = e / ss;

        u64 m0 = 0ull, m1 = 0ull;
#pragma unroll
        for (int h = 0; h < H; h++) {
            float ah = __shfl_sync(0xffffffffu, a, h);
            u64 a2 = pack2(ah, ah);
            m0 = ffma2(a2, yv[h].u[0], m0);
            m1 = ffma2(a2, yv[h].u[1], m1);
        }
        float r0, r1, r2, r3;
        unpack2(m0, r0, r1);
        unpack2(m1, r2, r3);
        red_add_v4(g_agg + (size_t)d * D + lane * 4, r0, r1, r2, r3);
    }
}

// ---------------- finalize: out = agg/deg + b (+relu, + BN stats) -----------
__global__ __launch_bounds__(256) void finalize_kernel(const float* __restrict__ bvec,
                                                       float* __restrict__ out,
                                                       int relu, int do_stats) {
    int c = threadIdx.x & 127;
    float bb = __ldg(&bvec[c]);
    float lsum = 0.f, lsq = 0.f;
    for (int i = blockIdx.x * blockDim.x + threadIdx.x; i < NN * D;
         i += gridDim.x * blockDim.x) {
        float v = g_agg[i] / (float)g_deg[i >> 7] + bb;
        if (relu) v = fmaxf(v, 0.f);
        out[i] = v;
        lsum += v; lsq += v * v;
    }
    if (do_stats) {
        __shared__ float s1[256], s2[256];
        s1[threadIdx.x] = lsum; s2[threadIdx.x] = lsq;
        __syncthreads();
        if (threadIdx.x < 128) {
            atomicAdd(&g_sum[threadIdx.x],   s1[threadIdx.x] + s1[threadIdx.x + 128]);
            atomicAdd(&g_sumsq[threadIdx.x], s2[threadIdx.x] + s2[threadIdx.x + 128]);
        }
    }
}

// ---------------- launch ----------------------------------------------------
static void run_gnn_layer(const float* xin_for_u, const float* Wu,
                          const float* cvec, const float* bvec,
                          float* outbuf, int relu, int do_stats)
{
    mma_y_kernel<<<dim3(12, 157), 256>>>();
    u_kernel<<<(NN * 32 + 255) / 256, 256>>>(xin_for_u, Wu, NN);
    zero_kernel<<<(NN * D + 255) / 256, 256>>>();
    scatter_kernel<<<(NN + 7) / 8, 256>>>(cvec);
    finalize_kernel<<<192, 256>>>(bvec, outbuf, relu, do_stats);
}

extern "C" void kernel_launch(void* const* d_in, const int* in_sizes, int n_in,
                              void* d_out, int out_size)
{
    const float* x  = (const float*)d_in[0];
    const int*   ei = (const int*)d_in[1];

    const float *Wlin[3], *Wu[3], *cv[3], *bv[3], *bng[2], *bnb[2];
    if (in_sizes[6] == H * D * D) {
        for (int l = 0; l < 3; l++) {
            Wlin[l] = (const float*)d_in[2 + 4 * l];
            Wu[l]   = (const float*)d_in[3 + 4 * l];
            cv[l]   = (const float*)d_in[4 + 4 * l];
            bv[l]   = (const float*)d_in[5 + 4 * l];
        }
        bng[0] = (const float*)d_in[14]; bnb[0] = (const float*)d_in[15];
        bng[1] = (const float*)d_in[16]; bnb[1] = (const float*)d_in[17];
    } else {
        Wlin[0] = (const float*)d_in[2];  Wu[0] = (const float*)d_in[3];
        cv[0]   = (const float*)d_in[4];  bv[0] = (const float*)d_in[5];
        bng[0]  = (const float*)d_in[6];  bnb[0] = (const float*)d_in[7];
        Wlin[1] = (const float*)d_in[8];  Wu[1] = (const float*)d_in[9];
        cv[1]   = (const float*)d_in[10]; bv[1] = (const float*)d_in[11];
        bng[1]  = (const float*)d_in[12]; bnb[1] = (const float*)d_in[13];
        Wlin[2] = (const float*)d_in[14]; Wu[2] = (const float*)d_in[15];
        cv[2]   = (const float*)d_in[16]; bv[2] = (const float*)d_in[17];
    }

    float* out = (float*)d_out;

    // degree by dst + CSR by src (identical across layers)
    deg_init_kernel<<<(NN + 255) / 256, 256>>>();
    deg_count_kernel<<<(NE + 255) / 256, 256>>>(ei);
    csr_zero_kernel<<<(NN + 255) / 256, 256>>>();
    csr_count_kernel<<<(NE + 255) / 256, 256>>>(ei);
    csr_scan_kernel<<<1, 1024>>>();
    csr_zero_kernel<<<(NN + 255) / 256, 256>>>();
    csr_fill_kernel<<<(NE + 255) / 256, 256>>>(ei);

    float* t = nullptr; float* hbuf = nullptr;
    cudaGetSymbolAddress((void**)&t, g_t);
    cudaGetSymbolAddress((void**)&hbuf, g_h);

    const int NCONV = (MPAD * D + 255) / 256;
    const int WCONV = (HO * D + 255) / 256;

    // layer 0
    convertx_kernel<<<NCONV, 256>>>(x);
    convertw_kernel<<<WCONV, 256>>>(Wlin[0]);
    run_gnn_layer(x, Wu[0], cv[0], bv[0], t, 1, 1);

    // layer 1 (BN0 fused into convert)
    bnconvert_kernel<<<NCONV, 256>>>(t, bng[0], bnb[0]);
    convertw_kernel<<<WCONV, 256>>>(Wlin[1]);
    run_gnn_layer(hbuf, Wu[1], cv[1], bv[1], t, 1, 1);

    // layer 2 (BN1 fused into convert; no relu/stats) -> d_out
    bnconvert_kernel<<<NCONV, 256>>>(t, bng[1], bnb[1]);
    convertw_kernel<<<WCONV, 256>>>(Wlin[2]);
    run_gnn_layer(hbuf, Wu[2], cv[2], bv[2], out, 0, 0);
}